// round 15
// baseline (speedup 1.0000x reference)
#include <cuda_runtime.h>
#include <math.h>

#define NG    64
#define ATOMS 32
#define NN    2048
#define HID   128
#define FEAT  64
#define GRID  148
#define HALF_F 11328   // floats per half-region: Ws 9216 + As 2112

// ---------------- scratch (device globals; no allocations allowed) ----------------
__device__ float d_isl[NG];
__device__ float d_x[NN * HID];
__device__ float d_q[NN * HID];
__device__ float d_k[NN * HID];
__device__ float d_v[NN * HID];
__device__ float d_vals[NN * HID];
__device__ float d_y0[NN * 128];
__device__ float d_y1[NN * 128];
// packed weights (k-major, zero-padded, values stored as tf32 bit patterns)
__device__ float d_Wq[128 * 384];
__device__ float d_Wp0[128 * 128];   // [k][o], o>=106 zero
__device__ float d_Wp1[128 * 128];   // [k][o], k>=106 or o>=85 zero
__device__ float d_Wp2[128 * 64];    // [k][o], k>=85 zero
__device__ float d_Bp0[128];
__device__ float d_Bp1[128];
// grid barrier state (monotone generation; safe across graph replays)
__device__ unsigned g_cnt = 0;
__device__ volatile unsigned g_gen = 0;

__device__ __forceinline__ void grid_sync() {
    __syncthreads();
    if (threadIdx.x == 0) {
        unsigned g = g_gen;
        __threadfence();
        if (atomicAdd(&g_cnt, 1u) == GRID - 1) {
            g_cnt = 0;
            __threadfence();
            g_gen = g + 1;
        } else {
            while (g_gen == g) { }
        }
        __threadfence();
    }
    __syncthreads();
}

__device__ __forceinline__ unsigned f2tf32(float f) {
    unsigned u;
    asm("cvt.rna.tf32.f32 %0, %1;" : "=r"(u) : "f"(f));
    return u;
}

__device__ __forceinline__ void mma_tf32(float c[4], const unsigned a[4],
                                         unsigned b0, unsigned b1) {
    asm volatile(
        "mma.sync.aligned.m16n8k8.row.col.f32.tf32.tf32.f32 "
        "{%0,%1,%2,%3}, {%4,%5,%6,%7}, {%8,%9}, {%0,%1,%2,%3};"
        : "+f"(c[0]), "+f"(c[1]), "+f"(c[2]), "+f"(c[3])
        : "r"(a[0]), "r"(a[1]), "r"(a[2]), "r"(a[3]), "r"(b0), "r"(b1));
}

// GEMM tile on a 128-thread half-block: stage W (tf32-packed) + A (convert),
// block-wide sync, then 16x64 MMA. Caller syncs before smem reuse.
template<int KSTEPS, int WGS>
__device__ __forceinline__ void gemm_tile(float* R, int stid, int rb, int cb,
                                          const float* __restrict__ A,
                                          const float* __restrict__ Wp,
                                          float c[2][4]) {
    float* Ws = R;            // [KSTEPS*8][72]
    float* As = R + 9216;     // [16][132]
#pragma unroll
    for (int lin = stid; lin < KSTEPS * 8 * 16; lin += 128) {
        int k = lin >> 4, cq = lin & 15;
        *(float4*)&Ws[k * 72 + cq * 4] = *(const float4*)&Wp[k * WGS + cb + cq * 4];
    }
#pragma unroll
    for (int lin = stid; lin < 16 * KSTEPS * 2; lin += 128) {
        int r = lin / (KSTEPS * 2), q = lin - r * (KSTEPS * 2);
        float4 av = *(const float4*)&A[(rb + r) * 128 + q * 4];
        uint4 tv;
        tv.x = f2tf32(av.x); tv.y = f2tf32(av.y);
        tv.z = f2tf32(av.z); tv.w = f2tf32(av.w);
        *(uint4*)&As[r * 132 + q * 4] = tv;
    }
    __syncthreads();

    int warp = stid >> 5, lane = stid & 31;
    int gid = lane >> 2, tig = lane & 3;
    const unsigned* Asu = (const unsigned*)As;
    const unsigned* Wsu = (const unsigned*)Ws;
    int nb = warp * 16 + gid;
    c[0][0] = c[0][1] = c[0][2] = c[0][3] = 0.f;
    c[1][0] = c[1][1] = c[1][2] = c[1][3] = 0.f;
#pragma unroll
    for (int s = 0; s < KSTEPS; s++) {
        int kk = s * 8 + tig;
        unsigned a[4];
        a[0] = Asu[gid * 132 + kk];
        a[1] = Asu[(gid + 8) * 132 + kk];
        a[2] = Asu[gid * 132 + kk + 4];
        a[3] = Asu[(gid + 8) * 132 + kk + 4];
        unsigned b00 = Wsu[kk * 72 + nb];
        unsigned b01 = Wsu[(kk + 4) * 72 + nb];
        unsigned b10 = Wsu[kk * 72 + nb + 8];
        unsigned b11 = Wsu[(kk + 4) * 72 + nb + 8];
        mma_tf32(c[0], a, b00, b01);
        mma_tf32(c[1], a, b10, b11);
    }
}

// ---------------- the single persistent kernel ----------------
__global__ void __launch_bounds__(256)
k_all(const float* __restrict__ h, const float* __restrict__ pos,
      const float* __restrict__ next_type, const int* __restrict__ batch,
      const float* __restrict__ W_emb, const float* __restrict__ Wqkv,
      const float* __restrict__ b_qkv,
      const float* __restrict__ W_g, const float* __restrict__ b_g,
      const float* __restrict__ W_t, const float* __restrict__ b_t,
      const float* __restrict__ Wd0, const float* __restrict__ bd0,
      const float* __restrict__ Wd1, const float* __restrict__ bd1,
      const float* __restrict__ Wd2, const float* __restrict__ bd2,
      float* __restrict__ out) {
    extern __shared__ float sm[];
    int tid = threadIdx.x, bid = blockIdx.x;
    int half = tid >> 7;          // 0 or 1
    int stid = tid & 127;         // sub-block tid
    float* R = sm + half * HALF_F;

    // ===== phase 0: setup (prep u<64, repack 64<=u<418) =====
    for (int it = 0; it < 3; it++) {
        int u = it * GRID + bid;
        if (u < NG) {
            float* nt  = sm;           // 64
            float* emb = sm + 64;      // 128
            int*   sc  = (int*)(sm + 192);  // 256
            int g = u, base = g * ATOMS;
            if (tid < FEAT) nt[tid] = next_type[g * FEAT + tid];
            __syncthreads();
            if (tid < HID) {
                const float* w = W_emb + tid * FEAT;
                float acc = 0.f;
#pragma unroll
                for (int f = 0; f < FEAT; f++) acc += nt[f] * w[f];
                emb[tid] = acc;
            }
            int cnt = 0;
#pragma unroll
            for (int i = tid; i < NN; i += 256) cnt += (batch[i] == g) ? 1 : 0;
            sc[tid] = cnt;
            __syncthreads();
            for (int s = 128; s > 0; s >>= 1) {
                if (tid < s) sc[tid] += sc[tid + s];
                __syncthreads();
            }
            if (tid == 0) d_isl[g] = rsqrtf((float)sc[0]);
#pragma unroll
            for (int v = 0; v < 4; v++) {
                int lin = tid + v * 256;
                int r = lin >> 5, kv = lin & 31;
                float4 hv = *(const float4*)&h[(base + r) * HID + kv * 4];
                float4 ev = *(const float4*)&emb[kv * 4];
                float4 o;
                o.x = hv.x * ev.x; o.y = hv.y * ev.y;
                o.z = hv.z * ev.z; o.w = hv.w * ev.w;
                *(float4*)&d_x[(base + r) * HID + kv * 4] = o;
            }
        } else {
            int uc = min(u, 417);
            int idx = (uc - NG) * 256 + tid;
            if (idx < 49152) {
                int k = idx / 384, o = idx - k * 384;
                d_Wq[idx] = __uint_as_float(f2tf32(Wqkv[o * 128 + k]));
            } else if (idx < 65536) {
                int e = idx - 49152;
                int k = e >> 7, o = e & 127;
                d_Wp0[e] = (o < 106) ? __uint_as_float(f2tf32(Wd0[o * 128 + k])) : 0.f;
            } else if (idx < 81920) {
                int e = idx - 65536;
                int k = e >> 7, o = e & 127;
                d_Wp1[e] = (o < 85 && k < 106) ? __uint_as_float(f2tf32(Wd1[o * 106 + k])) : 0.f;
            } else if (idx < 90112) {
                int e = idx - 81920;
                int k = e >> 6, o = e & 63;
                d_Wp2[e] = (k < 85) ? __uint_as_float(f2tf32(Wd2[o * 85 + k])) : 0.f;
            } else if (idx < 90240) {
                int e = idx - 90112;
                d_Bp0[e] = (e < 106) ? bd0[e] : 0.f;
            } else if (idx < 90368) {
                int e = idx - 90240;
                d_Bp1[e] = (e < 85) ? bd1[e] : 0.f;
            }
        }
        __syncthreads();
    }
    grid_sync();

    // ===== phase 1: qkv (768 units of 16r x 64c) =====
    for (int it = 0; it < 3; it++) {
        int u0 = it * (GRID * 2) + bid * 2 + half;
        int u = min(u0, 767);
        bool valid = (u0 < 768);
        int cb = (u % 6) * 64;
        int rb = (u / 6) * 16;
        float c[2][4];
        gemm_tile<16, 384>(R, stid, rb, cb, d_x, d_Wq, c);
        int warp = stid >> 5, lane = stid & 31;
        int gid = lane >> 2, tig = lane & 3;
        int row0 = rb + gid, row1 = rb + gid + 8;
        if (valid) {
#pragma unroll
            for (int nt2 = 0; nt2 < 2; nt2++) {
                int cg = cb + warp * 16 + nt2 * 8 + tig * 2;
                int which = cg >> 7;
                int lc = cg & 127;
                float* outb = (which == 0) ? d_q : ((which == 1) ? d_k : d_v);
                float bq0 = b_qkv[cg], bq1 = b_qkv[cg + 1];
                float2 o0, o1;
                o0.x = c[nt2][0] + bq0; o0.y = c[nt2][1] + bq1;
                o1.x = c[nt2][2] + bq0; o1.y = c[nt2][3] + bq1;
                *(float2*)&outb[row0 * 128 + lc] = o0;
                *(float2*)&outb[row1 * 128 + lc] = o1;
            }
        }
        __syncthreads();
    }
    grid_sync();

    // ===== phase 2: attention (256 units of 8 rows, full 256-thread block) =====
    for (int it = 0; it < 2; it++) {
        int u0 = it * GRID + bid;
        int u = min(u0, 255);
        bool valid = (u0 < 256);
        int g = u >> 2, quarter = u & 3;
        int base = g * ATOMS;
        int rbase = quarter * 8;

        float* sQt  = sm;             // [128][9]
        float* sKt  = sm + 1152;      // [128][32]
        float* sV   = sm + 5248;      // [32][128]
        float* sL   = sm + 9344;      // [8][32]
        float* sWg  = sm + 9600;      // 128
        float* sPos = sm + 9728;      // 96
        float* sGate= sm + 9824;      // 8
        float* sWt  = sm + 9832;      // 32

        {
            int kq = tid >> 3, r = tid & 7;
            float4 qa = *(const float4*)&d_q[(base + rbase + r) * HID + kq * 4];
            sQt[(kq * 4 + 0) * 9 + r] = qa.x;
            sQt[(kq * 4 + 1) * 9 + r] = qa.y;
            sQt[(kq * 4 + 2) * 9 + r] = qa.z;
            sQt[(kq * 4 + 3) * 9 + r] = qa.w;
        }
#pragma unroll
        for (int v = 0; v < 4; v++) {
            int lin = tid + v * 256;
            int r = lin & 31, kq = lin >> 5;
            float4 ka = *(const float4*)&d_k[(base + r) * HID + kq * 4];
            sKt[(kq * 4 + 0) * 32 + r] = ka.x;
            sKt[(kq * 4 + 1) * 32 + r] = ka.y;
            sKt[(kq * 4 + 2) * 32 + r] = ka.z;
            sKt[(kq * 4 + 3) * 32 + r] = ka.w;
        }
#pragma unroll
        for (int v = 0; v < 4; v++) {
            int lin = tid + v * 256;
            int r = lin >> 5, kv = lin & 31;
            *(float4*)&sV[r * 128 + kv * 4] = *(const float4*)&d_v[(base + r) * HID + kv * 4];
        }
        if (tid < 128) sWg[tid] = W_g[tid];
        if (tid < 96) sPos[tid] = pos[base * 3 + tid];
        if (tid < 32) sWt[tid] = W_t[tid];
        __syncthreads();

        int w = tid >> 5, lane = tid & 31;
        float invs = d_isl[g];
        float bgv = b_g[0];

        {
            const float* xr = d_x + (base + rbase + w) * HID;
            float p = 0.f;
#pragma unroll
            for (int k = lane; k < HID; k += 32) p += xr[k] * sWg[k];
#pragma unroll
            for (int o = 16; o; o >>= 1) p += __shfl_xor_sync(~0u, p, o);
            if (lane == 0) sGate[w] = 1.f / (1.f + __expf(-(p + bgv)));
        }

        int i = tid >> 5;
        int j = lane;
        float qk_e = 0.f, qk_o = 0.f;
#pragma unroll 8
        for (int k = 0; k < HID; k += 2) {
            qk_e += sQt[k * 9 + i] * sKt[k * 32 + j];
            qk_o += sQt[(k + 1) * 9 + i] * sKt[(k + 1) * 32 + j];
        }
        float qk = qk_e + qk_o;
        float btv = b_t[0];
        int gi = rbase + i;
        float dx = sPos[gi * 3 + 0] - sPos[j * 3 + 0];
        float dy = sPos[gi * 3 + 1] - sPos[j * 3 + 1];
        float dz = sPos[gi * 3 + 2] - sPos[j * 3 + 2];
        float d = sqrtf(fmaxf(dx * dx + dy * dy + dz * dz, 1e-12f));
        const float step = 10.f / 31.f;
        int b0 = __float2int_rn(d * (31.f / 10.f));
        int bs = min(max(b0 - 4, 0), 24);
        float t = btv;
#pragma unroll
        for (int bb = 0; bb < 8; bb++) {
            int b = bs + bb;
            float diff = d - (float)b * step;
            t += __expf(-10.f * diff * diff) * sWt[b];
        }
        sL[i * 32 + j] = qk * invs + t;
        __syncthreads();

        {
            float vv = sL[w * 32 + lane];
            float m = vv;
#pragma unroll
            for (int o = 16; o; o >>= 1) m = fmaxf(m, __shfl_xor_sync(~0u, m, o));
            float e = __expf(vv - m);
            float s = e;
#pragma unroll
            for (int o = 16; o; o >>= 1) s += __shfl_xor_sync(~0u, s, o);
            sL[w * 32 + lane] = e / s;
        }
        __syncthreads();

        {
            int rg = tid >> 5, cg = tid & 31;
            int c0 = cg * 4;
            float a0 = 0.f, a1 = 0.f, a2 = 0.f, a3 = 0.f;
#pragma unroll 8
            for (int jj = 0; jj < 32; jj++) {
                float p = sL[rg * 32 + jj];
                float4 vv = *(const float4*)&sV[jj * 128 + c0];
                a0 += p * vv.x; a1 += p * vv.y; a2 += p * vv.z; a3 += p * vv.w;
            }
            if (valid) {
                int grow = base + rbase + rg;
                float gg = sGate[rg];
                float4 xr = *(const float4*)&d_x[grow * HID + c0];
                float4 o;
                o.x = a0 * gg + xr.x; o.y = a1 * gg + xr.y;
                o.z = a2 * gg + xr.z; o.w = a3 * gg + xr.w;
                *(float4*)&d_vals[grow * HID + c0] = o;
            }
        }
        __syncthreads();
    }
    grid_sync();

    // ===== phase 3: mlp0 (256 units of 16r x 64c, SiLU) =====
    {
        int u0 = bid * 2 + half;
        int u = min(u0, 255);
        bool valid = (u0 < 256);
        int cb = (u & 1) * 64;
        int rb = (u >> 1) * 16;
        float c[2][4];
        gemm_tile<16, 128>(R, stid, rb, cb, d_vals, d_Wp0, c);
        int warp = stid >> 5, lane = stid & 31;
        int gid = lane >> 2, tig = lane & 3;
        int row0 = rb + gid, row1 = rb + gid + 8;
        if (valid) {
#pragma unroll
            for (int nt2 = 0; nt2 < 2; nt2++) {
                int cg = cb + warp * 16 + nt2 * 8 + tig * 2;
                float bq0 = d_Bp0[cg], bq1 = d_Bp0[cg + 1];
                float z, o0x, o0y, o1x, o1y;
                z = c[nt2][0] + bq0; o0x = z / (1.f + __expf(-z));
                z = c[nt2][1] + bq1; o0y = z / (1.f + __expf(-z));
                z = c[nt2][2] + bq0; o1x = z / (1.f + __expf(-z));
                z = c[nt2][3] + bq1; o1y = z / (1.f + __expf(-z));
                float2 a2;
                a2.x = o0x; a2.y = o0y;
                *(float2*)&d_y0[row0 * 128 + cg] = a2;
                a2.x = o1x; a2.y = o1y;
                *(float2*)&d_y0[row1 * 128 + cg] = a2;
            }
        }
    }
    grid_sync();

    // ===== phase 4: mlp1 (256 units, SiLU) =====
    {
        int u0 = bid * 2 + half;
        int u = min(u0, 255);
        bool valid = (u0 < 256);
        int cb = (u & 1) * 64;
        int rb = (u >> 1) * 16;
        float c[2][4];
        gemm_tile<14, 128>(R, stid, rb, cb, d_y0, d_Wp1, c);
        int warp = stid >> 5, lane = stid & 31;
        int gid = lane >> 2, tig = lane & 3;
        int row0 = rb + gid, row1 = rb + gid + 8;
        if (valid) {
#pragma unroll
            for (int nt2 = 0; nt2 < 2; nt2++) {
                int cg = cb + warp * 16 + nt2 * 8 + tig * 2;
                float bq0 = d_Bp1[cg], bq1 = d_Bp1[cg + 1];
                float z, o0x, o0y, o1x, o1y;
                z = c[nt2][0] + bq0; o0x = z / (1.f + __expf(-z));
                z = c[nt2][1] + bq1; o0y = z / (1.f + __expf(-z));
                z = c[nt2][2] + bq0; o1x = z / (1.f + __expf(-z));
                z = c[nt2][3] + bq1; o1y = z / (1.f + __expf(-z));
                float2 a2;
                a2.x = o0x; a2.y = o0y;
                *(float2*)&d_y1[row0 * 128 + cg] = a2;
                a2.x = o1x; a2.y = o1y;
                *(float2*)&d_y1[row1 * 128 + cg] = a2;
            }
        }
    }
    grid_sync();

    // ===== phase 5: mlp2 + log_softmax (128 units of 16r x 64c) =====
    {
        int u0 = bid * 2 + half;
        int u = min(u0, 127);
        bool valid = (u0 < 128);
        int rb = u * 16;
        float c[2][4];
        gemm_tile<11, 64>(R, stid, rb, 0, d_y1, d_Wp2, c);
        int warp = stid >> 5, lane = stid & 31;
        int gid = lane >> 2, tig = lane & 3;

        __syncthreads();             // done reading Ws; reuse region as sY[16][66]
        float* sY = R;
#pragma unroll
        for (int nt2 = 0; nt2 < 2; nt2++) {
            int lc = warp * 16 + nt2 * 8 + tig * 2;
            float bq0 = bd2[lc], bq1 = bd2[lc + 1];
            float2 o;
            o.x = c[nt2][0] + bq0; o.y = c[nt2][1] + bq1;
            *(float2*)&sY[gid * 66 + lc] = o;
            o.x = c[nt2][2] + bq0; o.y = c[nt2][3] + bq1;
            *(float2*)&sY[(gid + 8) * 66 + lc] = o;
        }
        __syncthreads();
#pragma unroll
        for (int rr = 0; rr < 4; rr++) {
            int r = warp * 4 + rr;
            float v0 = sY[r * 66 + lane];
            float v1 = sY[r * 66 + 32 + lane];
            float m = fmaxf(v0, v1);
#pragma unroll
            for (int o = 16; o; o >>= 1) m = fmaxf(m, __shfl_xor_sync(~0u, m, o));
            float s = __expf(v0 - m) + __expf(v1 - m);
#pragma unroll
            for (int o = 16; o; o >>= 1) s += __shfl_xor_sync(~0u, s, o);
            float ls = logf(s) + m;
            if (valid) {
                out[(rb + r) * 64 + lane] = v0 - ls;
                out[(rb + r) * 64 + 32 + lane] = v1 - ls;
            }
        }
    }
}

// ---------------- launch ----------------
extern "C" void kernel_launch(void* const* d_in, const int* in_sizes, int n_in,
                              void* d_out, int out_size) {
    const float* h     = (const float*)d_in[0];
    const float* pos   = (const float*)d_in[1];
    const float* nt    = (const float*)d_in[2];
    const int*   batch = (const int*)d_in[3];
    const float* W_emb = (const float*)d_in[4];
    const float* W_qkv = (const float*)d_in[5];
    const float* b_qkv = (const float*)d_in[6];
    // d_in[7]=W_b, d_in[8]=b_b : per-row bias, drops out of softmax
    const float* W_g   = (const float*)d_in[9];
    const float* b_g   = (const float*)d_in[10];
    const float* W_t   = (const float*)d_in[11];
    const float* b_t   = (const float*)d_in[12];
    const float* W_d0  = (const float*)d_in[13];
    const float* b_d0  = (const float*)d_in[14];
    const float* W_d1  = (const float*)d_in[15];
    const float* b_d1  = (const float*)d_in[16];
    const float* W_d2  = (const float*)d_in[17];
    const float* b_d2  = (const float*)d_in[18];
    float* out = (float*)d_out;

    const int smem = 2 * HALF_F * 4;   // 90624 B

    cudaFuncSetAttribute(k_all, cudaFuncAttributeMaxDynamicSharedMemorySize, 96 * 1024);

    k_all<<<GRID, 256, smem>>>(h, pos, nt, batch, W_emb, W_qkv, b_qkv,
                               W_g, b_g, W_t, b_t,
                               W_d0, b_d0, W_d1, b_d1, W_d2, b_d2, out);
}

// round 16
// speedup vs baseline: 1.4283x; 1.4283x over previous
#include <cuda_runtime.h>
#include <math.h>

#define NG    64
#define ATOMS 32
#define NN    2048
#define HID   128
#define FEAT  64

// ---------------- scratch (device globals; no allocations allowed) ----------------
__device__ float d_vals[NN * HID];

__device__ __forceinline__ unsigned f2tf32(float f) {
    unsigned u;
    asm("cvt.rna.tf32.f32 %0, %1;" : "=r"(u) : "f"(f));
    return u;
}

__device__ __forceinline__ void mma_tf32(float c[4], const unsigned a[4],
                                         unsigned b0, unsigned b1) {
    asm volatile(
        "mma.sync.aligned.m16n8k8.row.col.f32.tf32.tf32.f32 "
        "{%0,%1,%2,%3}, {%4,%5,%6,%7}, {%8,%9}, {%0,%1,%2,%3};"
        : "+f"(c[0]), "+f"(c[1]), "+f"(c[2]), "+f"(c[3])
        : "r"(a[0]), "r"(a[1]), "r"(a[2]), "r"(a[3]), "r"(b0), "r"(b1));
}

// ================= K1: per-graph fused emb + x + qkv + attention ================
// 128 blocks (2 per graph, 16 q-rows each), 256 threads.
// smem float offsets:
//  sW 0 (8448=[64][132])  sXt 8448 ([32][132] tf32)  sX 12672 ([32][128] fp32)
//  sQt 16768 ([128][17])  sKt 18944 ([128][34])      sV 23296 ([32][132])
//  sL 27520 ([16][34])    sEmb 28064(128) sNt 28192(64) sPos 28256(96)
//  sWg 28352(128) sWt 28480(32) sGate 28512(16) sIsl 28528(1) -> 28544 fl
#define KG_SMEM (28544 * 4)
__global__ void __launch_bounds__(256)
k_graph(const float* __restrict__ h, const float* __restrict__ pos,
        const float* __restrict__ next_type, const int* __restrict__ batch,
        const float* __restrict__ W_emb, const float* __restrict__ Wqkv,
        const float* __restrict__ b_qkv,
        const float* __restrict__ W_g, const float* __restrict__ b_g,
        const float* __restrict__ W_t, const float* __restrict__ b_t) {
    extern __shared__ float sm[];
    float* sW   = sm;
    float* sXt  = sm + 8448;
    float* sX   = sm + 12672;
    float* sQt  = sm + 16768;
    float* sKt  = sm + 18944;
    float* sV   = sm + 23296;
    float* sL   = sm + 27520;
    float* sEmb = sm + 28064;
    float* sNt  = sm + 28192;
    float* sPos = sm + 28256;
    float* sWg  = sm + 28352;
    float* sWt  = sm + 28480;
    float* sGate= sm + 28512;
    float* sIsl = sm + 28528;

    int tid = threadIdx.x;
    int u = blockIdx.x;
    int g = u >> 1, half = u & 1;
    int base = g * ATOMS;
    int rbase = half * 16;
    int warp = tid >> 5, lane = tid & 31;
    int gid = lane >> 2, tig = lane & 3;

    // ---- phase A: stage small inputs + per-graph length count ----
    if (tid < FEAT) sNt[tid] = next_type[g * FEAT + tid];
    if (tid < 96) sPos[tid] = pos[base * 3 + tid];
    if (tid < 128) sWg[tid] = W_g[tid];
    if (tid < 32) sWt[tid] = W_t[tid];
    {
        int cnt = 0;
#pragma unroll
        for (int i = tid; i < NN; i += 256) cnt += (batch[i] == g) ? 1 : 0;
#pragma unroll
        for (int o = 16; o; o >>= 1) cnt += __shfl_xor_sync(~0u, cnt, o);
        if (lane == 0) sL[warp] = (float)cnt;
    }
    __syncthreads();

    // ---- phase B: emb (128x64 GEMV) + isl ----
    if (tid < HID) {
        const float* w = W_emb + tid * FEAT;
        float acc = 0.f;
#pragma unroll
        for (int f = 0; f < FEAT; f++) acc += sNt[f] * w[f];
        sEmb[tid] = acc;
    }
    if (tid == 0) {
        float s = 0.f;
#pragma unroll
        for (int i = 0; i < 8; i++) s += sL[i];
        sIsl[0] = rsqrtf(s);
    }
    __syncthreads();

    // ---- phase C: x = h * emb for all 32 rows (fp32 + tf32 copies) ----
#pragma unroll
    for (int v = 0; v < 4; v++) {
        int lin = tid + v * 256;
        int r = lin >> 5, q4 = lin & 31;
        float4 hv = *(const float4*)&h[(base + r) * HID + q4 * 4];
        float4 ev = *(const float4*)&sEmb[q4 * 4];
        float4 xo;
        xo.x = hv.x * ev.x; xo.y = hv.y * ev.y;
        xo.z = hv.z * ev.z; xo.w = hv.w * ev.w;
        *(float4*)&sX[r * 128 + q4 * 4] = xo;
        uint4 tv;
        tv.x = f2tf32(xo.x); tv.y = f2tf32(xo.y);
        tv.z = f2tf32(xo.z); tv.w = f2tf32(xo.w);
        *(uint4*)&sXt[r * 132 + q4 * 4] = tv;
    }
    __syncthreads();

    // ---- phase D: qkv via 6 streamed W chunks (64 out-rows x 128 k each) ----
    const unsigned* Au = (const unsigned*)sXt;
    for (int ch = 0; ch < 6; ch++) {
        int cb = ch * 64;
        // stage W chunk (row-major global -> out-major smem, tf32)
#pragma unroll
        for (int lin = tid; lin < 2048; lin += 256) {
            int o = lin >> 5, q4 = lin & 31;
            float4 wv = *(const float4*)&Wqkv[(cb + o) * 128 + q4 * 4];
            uint4 tv;
            tv.x = f2tf32(wv.x); tv.y = f2tf32(wv.y);
            tv.z = f2tf32(wv.z); tv.w = f2tf32(wv.w);
            *(uint4*)&sW[o * 132 + q4 * 4] = tv;
        }
        __syncthreads();
        const unsigned* Wu = (const unsigned*)sW;

        if (ch < 2) {
            // q: 16 own rows, 8 warps x 8 cols
            float c[4] = {0.f, 0.f, 0.f, 0.f};
            int nb = warp * 8 + gid;
#pragma unroll
            for (int s = 0; s < 16; s++) {
                int kk = s * 8 + tig;
                unsigned a[4];
                a[0] = Au[(rbase + gid) * 132 + kk];
                a[1] = Au[(rbase + gid + 8) * 132 + kk];
                a[2] = Au[(rbase + gid) * 132 + kk + 4];
                a[3] = Au[(rbase + gid + 8) * 132 + kk + 4];
                mma_tf32(c, a, Wu[nb * 132 + kk], Wu[nb * 132 + kk + 4]);
            }
            int lc = cb + warp * 8 + tig * 2;       // q col 0..127
            float b0 = b_qkv[lc], b1 = b_qkv[lc + 1];
            sQt[lc * 17 + gid]           = c[0] + b0;
            sQt[(lc + 1) * 17 + gid]     = c[1] + b1;
            sQt[lc * 17 + gid + 8]       = c[2] + b0;
            sQt[(lc + 1) * 17 + gid + 8] = c[3] + b1;
        } else {
            // k or v: all 32 rows; warps 0-3 rows 0-15, warps 4-7 rows 16-31
            int rt = warp >> 2, w4 = warp & 3;
            int r0 = rt * 16 + gid;
            float c[2][4] = {};
#pragma unroll
            for (int s = 0; s < 16; s++) {
                int kk = s * 8 + tig;
                unsigned a[4];
                a[0] = Au[r0 * 132 + kk];
                a[1] = Au[(r0 + 8) * 132 + kk];
                a[2] = Au[r0 * 132 + kk + 4];
                a[3] = Au[(r0 + 8) * 132 + kk + 4];
                int nb0 = w4 * 16 + gid;
                mma_tf32(c[0], a, Wu[nb0 * 132 + kk], Wu[nb0 * 132 + kk + 4]);
                mma_tf32(c[1], a, Wu[(nb0 + 8) * 132 + kk], Wu[(nb0 + 8) * 132 + kk + 4]);
            }
            bool isk = (ch < 4);
            int lcb = (ch & 1) * 64 + w4 * 16;
#pragma unroll
            for (int nt2 = 0; nt2 < 2; nt2++) {
                int lc = lcb + nt2 * 8 + tig * 2;
                int gcol = (isk ? 128 : 256) + lc;
                float b0 = b_qkv[gcol], b1 = b_qkv[gcol + 1];
                if (isk) {
                    sKt[lc * 34 + r0]           = c[nt2][0] + b0;
                    sKt[(lc + 1) * 34 + r0]     = c[nt2][1] + b1;
                    sKt[lc * 34 + r0 + 8]       = c[nt2][2] + b0;
                    sKt[(lc + 1) * 34 + r0 + 8] = c[nt2][3] + b1;
                } else {
                    sV[r0 * 132 + lc]           = c[nt2][0] + b0;
                    sV[r0 * 132 + lc + 1]       = c[nt2][1] + b1;
                    sV[(r0 + 8) * 132 + lc]     = c[nt2][2] + b0;
                    sV[(r0 + 8) * 132 + lc + 1] = c[nt2][3] + b1;
                }
            }
        }
        __syncthreads();
    }

    // ---- phase E: attention (16 q-rows vs 32 keys) ----
    float invs = sIsl[0];
    float bgv = b_g[0];
    // gate: 8 warps x 2 rows
#pragma unroll
    for (int rr = 0; rr < 2; rr++) {
        int row = warp * 2 + rr;
        const float* xr = sX + (rbase + row) * 128;
        float p = 0.f;
#pragma unroll
        for (int k = lane; k < HID; k += 32) p += xr[k] * sWg[k];
#pragma unroll
        for (int o = 16; o; o >>= 1) p += __shfl_xor_sync(~0u, p, o);
        if (lane == 0) sGate[row] = 1.f / (1.f + __expf(-(p + bgv)));
    }

    // logits: thread -> (i = tid>>4, cols j0, j0+1)
    {
        int i = tid >> 4;
        int j0 = (tid & 15) * 2;
        float qk0 = 0.f, qk1 = 0.f;
#pragma unroll 8
        for (int k = 0; k < HID; k++) {
            float qa = sQt[k * 17 + i];
            float2 kb = *(const float2*)&sKt[k * 34 + j0];
            qk0 += qa * kb.x;
            qk1 += qa * kb.y;
        }
        float btv = b_t[0];
        int gi = rbase + i;
        float px = sPos[gi * 3 + 0], py = sPos[gi * 3 + 1], pz = sPos[gi * 3 + 2];
        const float step = 10.f / 31.f;
        float qkp[2] = {qk0, qk1};
#pragma unroll
        for (int jj = 0; jj < 2; jj++) {
            int j = j0 + jj;
            float dx = px - sPos[j * 3 + 0];
            float dy = py - sPos[j * 3 + 1];
            float dz = pz - sPos[j * 3 + 2];
            float d = sqrtf(fmaxf(dx * dx + dy * dy + dz * dz, 1e-12f));
            int b0i = __float2int_rn(d * (31.f / 10.f));
            int bs = min(max(b0i - 4, 0), 24);
            float t = btv;
#pragma unroll
            for (int bb = 0; bb < 8; bb++) {
                int b = bs + bb;
                float diff = d - (float)b * step;
                t += __expf(-10.f * diff * diff) * sWt[b];
            }
            sL[i * 34 + j] = qkp[jj] * invs + t;
        }
    }
    __syncthreads();

    // softmax: 8 warps x 2 rows
#pragma unroll
    for (int rr = 0; rr < 2; rr++) {
        int r = warp * 2 + rr;
        float vv = sL[r * 34 + lane];
        float m = vv;
#pragma unroll
        for (int o = 16; o; o >>= 1) m = fmaxf(m, __shfl_xor_sync(~0u, m, o));
        float e = __expf(vv - m);
        float s = e;
#pragma unroll
        for (int o = 16; o; o >>= 1) s += __shfl_xor_sync(~0u, s, o);
        sL[r * 34 + lane] = e / s;
    }
    __syncthreads();

    // out = (attn @ V) * gate + x : 2 rows x 4 cols per thread
    {
        int rg = tid >> 5, cg = tid & 31;
        int ir = rg * 2, c0 = cg * 4;
        float a00 = 0.f, a01 = 0.f, a02 = 0.f, a03 = 0.f;
        float a10 = 0.f, a11 = 0.f, a12 = 0.f, a13 = 0.f;
#pragma unroll 8
        for (int j = 0; j < 32; j++) {
            float p0 = sL[ir * 34 + j];
            float p1 = sL[(ir + 1) * 34 + j];
            float4 vv = *(const float4*)&sV[j * 132 + c0];
            a00 += p0 * vv.x; a01 += p0 * vv.y; a02 += p0 * vv.z; a03 += p0 * vv.w;
            a10 += p1 * vv.x; a11 += p1 * vv.y; a12 += p1 * vv.z; a13 += p1 * vv.w;
        }
        int grow = base + rbase + ir;
        float gg = sGate[ir];
        float4 xr = *(const float4*)&sX[(rbase + ir) * 128 + c0];
        float4 o;
        o.x = a00 * gg + xr.x; o.y = a01 * gg + xr.y;
        o.z = a02 * gg + xr.z; o.w = a03 * gg + xr.w;
        *(float4*)&d_vals[grow * 128 + c0] = o;
        gg = sGate[ir + 1];
        xr = *(const float4*)&sX[(rbase + ir + 1) * 128 + c0];
        o.x = a10 * gg + xr.x; o.y = a11 * gg + xr.y;
        o.z = a12 * gg + xr.z; o.w = a13 * gg + xr.w;
        *(float4*)&d_vals[(grow + 1) * 128 + c0] = o;
    }
}

// ================= K2: per-16-row fused dense head (3 layers + log_softmax) =====
// 128 blocks, 256 threads. Weights streamed per 64-out chunk from original layout.
// smem float offsets: sW 0 ([64][132]=8448), sA 8448 ([16][132]), sY0 10560,
//                     sY1 12672 -> total 14784 fl
#define KH_SMEM (14784 * 4)
__global__ void __launch_bounds__(256)
k_head(const float* __restrict__ Wd0, const float* __restrict__ bd0,
       const float* __restrict__ Wd1, const float* __restrict__ bd1,
       const float* __restrict__ Wd2, const float* __restrict__ bd2,
       float* __restrict__ out) {
    extern __shared__ float sm[];
    float* sW  = sm;
    float* sA  = sm + 8448;
    float* sY0 = sm + 10560;
    float* sY1 = sm + 12672;

    int tid = threadIdx.x;
    int rb = blockIdx.x * 16;
    int warp = tid >> 5, lane = tid & 31;
    int gid = lane >> 2, tig = lane & 3;

    // stage A (16 rows of d_vals, tf32)
#pragma unroll
    for (int lin = tid; lin < 512; lin += 256) {
        int r = lin >> 5, q4 = lin & 31;
        float4 av = *(const float4*)&d_vals[(rb + r) * 128 + q4 * 4];
        uint4 tv;
        tv.x = f2tf32(av.x); tv.y = f2tf32(av.y);
        tv.z = f2tf32(av.z); tv.w = f2tf32(av.w);
        *(uint4*)&sA[r * 132 + q4 * 4] = tv;
    }
    __syncthreads();

    const unsigned* Wu = (const unsigned*)sW;
    unsigned* Y0u = (unsigned*)sY0;
    unsigned* Y1u = (unsigned*)sY1;

    // ---- layer 0: 128 -> 106(pad 128), SiLU. 2 chunks of 64 out-rows ----
    for (int ch = 0; ch < 2; ch++) {
        int cb = ch * 64;
#pragma unroll
        for (int lin = tid; lin < 2048; lin += 256) {
            int o = lin >> 5, q4 = lin & 31;
            uint4 tv = {0u, 0u, 0u, 0u};
            if (cb + o < 106) {
                float4 wv = *(const float4*)&Wd0[(cb + o) * 128 + q4 * 4];
                tv.x = f2tf32(wv.x); tv.y = f2tf32(wv.y);
                tv.z = f2tf32(wv.z); tv.w = f2tf32(wv.w);
            }
            *(uint4*)&sW[o * 132 + q4 * 4] = tv;
        }
        __syncthreads();
        const unsigned* Au = (const unsigned*)sA;
        float c[4] = {0.f, 0.f, 0.f, 0.f};
        int nb = warp * 8 + gid;
#pragma unroll
        for (int s = 0; s < 16; s++) {
            int kk = s * 8 + tig;
            unsigned a[4];
            a[0] = Au[gid * 132 + kk];
            a[1] = Au[(gid + 8) * 132 + kk];
            a[2] = Au[gid * 132 + kk + 4];
            a[3] = Au[(gid + 8) * 132 + kk + 4];
            mma_tf32(c, a, Wu[nb * 132 + kk], Wu[nb * 132 + kk + 4]);
        }
        int cg = cb + warp * 8 + tig * 2;
        float b0 = (cg < 106) ? bd0[cg] : 0.f;
        float b1 = (cg + 1 < 106) ? bd0[cg + 1] : 0.f;
        float z;
        z = c[0] + b0; Y0u[gid * 132 + cg]           = f2tf32(z / (1.f + __expf(-z)));
        z = c[1] + b1; Y0u[gid * 132 + cg + 1]       = f2tf32(z / (1.f + __expf(-z)));
        z = c[2] + b0; Y0u[(gid + 8) * 132 + cg]     = f2tf32(z / (1.f + __expf(-z)));
        z = c[3] + b1; Y0u[(gid + 8) * 132 + cg + 1] = f2tf32(z / (1.f + __expf(-z)));
        __syncthreads();
    }

    // ---- layer 1: 106 -> 85(pad 128), SiLU. KSTEPS=14 (k to 112, pad 0) ----
    for (int ch = 0; ch < 2; ch++) {
        int cb = ch * 64;
#pragma unroll
        for (int lin = tid; lin < 3584; lin += 256) {   // 64 rows x 56 float2
            int o = lin / 56, p2 = lin - o * 56;
            int k = p2 * 2;
            float2 wv = {0.f, 0.f};
            if (cb + o < 85 && k < 106)
                wv = *(const float2*)&Wd1[(cb + o) * 106 + k];
            unsigned t0 = f2tf32(wv.x), t1 = f2tf32(wv.y);
            *(uint2*)&sW[o * 132 + k] = make_uint2(t0, t1);
        }
        // zero-fill k = 112..131 not needed (KSTEPS=14 reads only k<112)
        __syncthreads();
        float c[4] = {0.f, 0.f, 0.f, 0.f};
        int nb = warp * 8 + gid;
#pragma unroll
        for (int s = 0; s < 14; s++) {
            int kk = s * 8 + tig;
            unsigned a[4];
            a[0] = Y0u[gid * 132 + kk];
            a[1] = Y0u[(gid + 8) * 132 + kk];
            a[2] = Y0u[gid * 132 + kk + 4];
            a[3] = Y0u[(gid + 8) * 132 + kk + 4];
            mma_tf32(c, a, Wu[nb * 132 + kk], Wu[nb * 132 + kk + 4]);
        }
        int cg = cb + warp * 8 + tig * 2;
        float b0 = (cg < 85) ? bd1[cg] : 0.f;
        float b1 = (cg + 1 < 85) ? bd1[cg + 1] : 0.f;
        float z;
        z = c[0] + b0; Y1u[gid * 132 + cg]           = f2tf32(z / (1.f + __expf(-z)));
        z = c[1] + b1; Y1u[gid * 132 + cg + 1]       = f2tf32(z / (1.f + __expf(-z)));
        z = c[2] + b0; Y1u[(gid + 8) * 132 + cg]     = f2tf32(z / (1.f + __expf(-z)));
        z = c[3] + b1; Y1u[(gid + 8) * 132 + cg + 1] = f2tf32(z / (1.f + __expf(-z)));
        __syncthreads();
    }

    // ---- layer 2: 85 -> 64, linear. KSTEPS=11 (k to 88, pad 0). 1 chunk ----
    float c2[4] = {0.f, 0.f, 0.f, 0.f};
    {
#pragma unroll
        for (int lin = tid; lin < 5632; lin += 256) {   // 64 rows x 88 scalars
            int o = lin / 88, k = lin - o * 88;
            float wv = (k < 85) ? Wd2[o * 85 + k] : 0.f;
            sW[o * 132 + k] = __uint_as_float(f2tf32(wv));
        }
        __syncthreads();
        int nb = warp * 8 + gid;
#pragma unroll
        for (int s = 0; s < 11; s++) {
            int kk = s * 8 + tig;
            unsigned a[4];
            a[0] = Y1u[gid * 132 + kk];
            a[1] = Y1u[(gid + 8) * 132 + kk];
            a[2] = Y1u[gid * 132 + kk + 4];
            a[3] = Y1u[(gid + 8) * 132 + kk + 4];
            mma_tf32(c2, a, Wu[nb * 132 + kk], Wu[nb * 132 + kk + 4]);
        }
    }
    __syncthreads();   // done reading sW; reuse as sY[16][66]

    float* sY = sW;
    {
        int lc = warp * 8 + tig * 2;
        float b0 = bd2[lc], b1 = bd2[lc + 1];
        sY[gid * 66 + lc]           = c2[0] + b0;
        sY[gid * 66 + lc + 1]       = c2[1] + b1;
        sY[(gid + 8) * 66 + lc]     = c2[2] + b0;
        sY[(gid + 8) * 66 + lc + 1] = c2[3] + b1;
    }
    __syncthreads();

    // log_softmax: 8 warps x 2 rows
#pragma unroll
    for (int rr = 0; rr < 2; rr++) {
        int r = warp * 2 + rr;
        float v0 = sY[r * 66 + lane];
        float v1 = sY[r * 66 + 32 + lane];
        float m = fmaxf(v0, v1);
#pragma unroll
        for (int o = 16; o; o >>= 1) m = fmaxf(m, __shfl_xor_sync(~0u, m, o));
        float s = __expf(v0 - m) + __expf(v1 - m);
#pragma unroll
        for (int o = 16; o; o >>= 1) s += __shfl_xor_sync(~0u, s, o);
        float ls = logf(s) + m;
        out[(rb + r) * 64 + lane] = v0 - ls;
        out[(rb + r) * 64 + 32 + lane] = v1 - ls;
    }
}

// ---------------- launch ----------------
extern "C" void kernel_launch(void* const* d_in, const int* in_sizes, int n_in,
                              void* d_out, int out_size) {
    const float* h     = (const float*)d_in[0];
    const float* pos   = (const float*)d_in[1];
    const float* nt    = (const float*)d_in[2];
    const int*   batch = (const int*)d_in[3];
    const float* W_emb = (const float*)d_in[4];
    const float* W_qkv = (const float*)d_in[5];
    const float* b_qkv = (const float*)d_in[6];
    // d_in[7]=W_b, d_in[8]=b_b : per-row bias, drops out of softmax
    const float* W_g   = (const float*)d_in[9];
    const float* b_g   = (const float*)d_in[10];
    const float* W_t   = (const float*)d_in[11];
    const float* b_t   = (const float*)d_in[12];
    const float* W_d0  = (const float*)d_in[13];
    const float* b_d0  = (const float*)d_in[14];
    const float* W_d1  = (const float*)d_in[15];
    const float* b_d1  = (const float*)d_in[16];
    const float* W_d2  = (const float*)d_in[17];
    const float* b_d2  = (const float*)d_in[18];
    float* out = (float*)d_out;

    cudaFuncSetAttribute(k_graph, cudaFuncAttributeMaxDynamicSharedMemorySize, KG_SMEM);
    cudaFuncSetAttribute(k_head, cudaFuncAttributeMaxDynamicSharedMemorySize, KH_SMEM);

    k_graph<<<128, 256, KG_SMEM>>>(h, pos, nt, batch, W_emb, W_qkv, b_qkv,
                                   W_g, b_g, W_t, b_t);
    k_head<<<128, 256, KH_SMEM>>>(W_d0, b_d0, W_d1, b_d1, W_d2, b_d2, out);
}